// round 1
// baseline (speedup 1.0000x reference)
#include <cuda_runtime.h>
#include <cstdint>

// Problem shape (fixed by setup_inputs): B=64, T=256, P=1024, D=1024
#define BATCH 64
#define TT    256
#define PP    1024
#define DD    1024
#define MM    (BATCH * TT)   // 16384 GEMM rows

#define DECAY 0.9f
#define V_TH  1.0f

// 64 MB scratch for currents (B,T,D) — device global per allocation rules.
__device__ float g_currents[(size_t)MM * DD];

// ---------------------------------------------------------------------------
// GEMM: C[M,D] = S[M,P] @ W[P,D], fp32, row-major.
// Tile: 128x128 block, BK=16, 256 threads, 8x8 per-thread register tile.
// ---------------------------------------------------------------------------
#define BM 128
#define BN 128
#define BK 16
#define TM 8
#define TN 8

__global__ __launch_bounds__(256, 2)
void lif_gemm_kernel(const float* __restrict__ A,   // spikes [M, P]
                     const float* __restrict__ W,   // weights [P, D]
                     float* __restrict__ C)         // currents [M, D]
{
    __shared__ float As[BK][BM];   // transposed A tile
    __shared__ float Bs[BK][BN];

    const int tid = threadIdx.x;
    const int bm = blockIdx.y * BM;
    const int bn = blockIdx.x * BN;

    const int tx = tid & 15;       // 0..15 -> N direction
    const int ty = tid >> 4;       // 0..15 -> M direction

    // Global-load assignments (each thread: 2x float4 of A, 2x float4 of W)
    const int a_row = tid >> 2;          // 0..63
    const int a_col = (tid & 3) * 4;     // 0,4,8,12  (k within tile)
    const int b_row = tid >> 5;          // 0..7      (k within tile)
    const int b_col = (tid & 31) * 4;    // 0..124

    float acc[TM][TN];
    #pragma unroll
    for (int i = 0; i < TM; i++)
        #pragma unroll
        for (int j = 0; j < TN; j++)
            acc[i][j] = 0.0f;

    for (int k0 = 0; k0 < PP; k0 += BK) {
        // Prefetch to registers
        const float4 a0 = *(const float4*)&A[(size_t)(bm + a_row)       * PP + k0 + a_col];
        const float4 a1 = *(const float4*)&A[(size_t)(bm + a_row + 64)  * PP + k0 + a_col];
        const float4 w0 = *(const float4*)&W[(size_t)(k0 + b_row)       * DD + bn + b_col];
        const float4 w1 = *(const float4*)&W[(size_t)(k0 + b_row + 8)   * DD + bn + b_col];

        __syncthreads();   // previous iteration's reads done before overwrite

        // A tile stored transposed: As[k][m]
        As[a_col + 0][a_row]      = a0.x;
        As[a_col + 1][a_row]      = a0.y;
        As[a_col + 2][a_row]      = a0.z;
        As[a_col + 3][a_row]      = a0.w;
        As[a_col + 0][a_row + 64] = a1.x;
        As[a_col + 1][a_row + 64] = a1.y;
        As[a_col + 2][a_row + 64] = a1.z;
        As[a_col + 3][a_row + 64] = a1.w;

        *(float4*)&Bs[b_row][b_col]     = w0;
        *(float4*)&Bs[b_row + 8][b_col] = w1;

        __syncthreads();

        #pragma unroll
        for (int k = 0; k < BK; k++) {
            float a[TM], b[TN];
            // vectorized smem reads (two float4 each)
            *(float4*)&a[0] = *(const float4*)&As[k][ty * TM];
            *(float4*)&a[4] = *(const float4*)&As[k][ty * TM + 4];
            *(float4*)&b[0] = *(const float4*)&Bs[k][tx * TN];
            *(float4*)&b[4] = *(const float4*)&Bs[k][tx * TN + 4];
            #pragma unroll
            for (int i = 0; i < TM; i++)
                #pragma unroll
                for (int j = 0; j < TN; j++)
                    acc[i][j] = fmaf(a[i], b[j], acc[i][j]);
        }
    }

    // Epilogue: vectorized stores
    #pragma unroll
    for (int i = 0; i < TM; i++) {
        float* crow = &C[(size_t)(bm + ty * TM + i) * DD + bn + tx * TN];
        float4 v0 = make_float4(acc[i][0], acc[i][1], acc[i][2], acc[i][3]);
        float4 v1 = make_float4(acc[i][4], acc[i][5], acc[i][6], acc[i][7]);
        *(float4*)&crow[0] = v0;
        *(float4*)&crow[4] = v1;
    }
}

// ---------------------------------------------------------------------------
// LIF scan over time. One thread per (b, d). Output: voltage then spikes,
// each (B, T, D) fp32, concatenated in d_out.
// ---------------------------------------------------------------------------
__global__ __launch_bounds__(256)
void lif_scan_kernel(const float* __restrict__ cur,  // [B, T, D]
                     float* __restrict__ vout,       // [B, T, D]
                     float* __restrict__ sout)       // [B, T, D]
{
    const int idx = blockIdx.x * blockDim.x + threadIdx.x;  // 0 .. B*D-1
    if (idx >= BATCH * DD) return;
    const int b = idx / DD;
    const int d = idx - b * DD;

    size_t base = (size_t)b * TT * DD + d;

    float v = 0.0f;
    #pragma unroll 4
    for (int t = 0; t < TT; t++) {
        const size_t off = base + (size_t)t * DD;
        float c = cur[off];
        float v_new = fmaf(DECAY, v, c);          // leak + integrate
        float s = (v_new >= V_TH) ? 1.0f : 0.0f;  // threshold
        vout[off] = v_new;
        sout[off] = s;
        v = v_new * (1.0f - s);                   // reset-to-zero on spike
    }
}

// ---------------------------------------------------------------------------
// Launch
// ---------------------------------------------------------------------------
extern "C" void kernel_launch(void* const* d_in, const int* in_sizes, int n_in,
                              void* d_out, int out_size)
{
    // metadata order: prv_voltage (unused), prv_spikes, weights
    const float* spikes  = (const float*)d_in[1];
    const float* weights = (const float*)d_in[2];
    float* out = (float*)d_out;

    float* currents;
    cudaGetSymbolAddress((void**)&currents, g_currents);

    // GEMM: currents = spikes @ weights
    dim3 gemm_grid(DD / BN, MM / BM);   // (8, 128)
    lif_gemm_kernel<<<gemm_grid, 256>>>(spikes, weights, currents);

    // Scan: voltage -> out[0 : B*T*D], spikes -> out[B*T*D : 2*B*T*D]
    const size_t n_elem = (size_t)BATCH * TT * DD;
    float* vout = out;
    float* sout = out + n_elem;
    const int nthreads = BATCH * DD;    // 65536
    lif_scan_kernel<<<(nthreads + 255) / 256, 256>>>(currents, vout, sout);
}

// round 4
// speedup vs baseline: 1.6871x; 1.6871x over previous
#include <cuda_runtime.h>
#include <cstdint>

// Problem shape (fixed): B=64, T=256, P=1024, D=1024
#define BATCH 64
#define TT    256
#define PP    1024
#define DD    1024
#define MM    (BATCH * TT)

#define DECAY 0.9f
#define V_TH  1.0f

// Device-global scratch (no allocs allowed).
__device__ float    g_currents[(size_t)MM * DD];     // 64 MB
__device__ uint32_t g_bits[(size_t)MM * (PP / 32)];  //  2 MB spike bitmask

// ---------------------------------------------------------------------------
// prep_bits: spikes (fp32 {0,1}) -> bitmask, order-preserving (bit b of word w
// = spike at p = w*32 + b). One warp per row.
// ---------------------------------------------------------------------------
__global__ __launch_bounds__(256)
void prep_bits(const float* __restrict__ S, uint32_t* __restrict__ bits)
{
    const int warp = threadIdx.x >> 5;
    const int lane = threadIdx.x & 31;
    const int row = blockIdx.x * 8 + warp;           // 16384 rows
    const float* src = S + (size_t)row * PP;
    uint32_t* dst = bits + (size_t)row * (PP / 32);
    #pragma unroll
    for (int w = 0; w < PP / 32; w++) {
        const float v = src[w * 32 + lane];
        const uint32_t m = __ballot_sync(0xFFFFFFFFu, v != 0.0f);
        if (lane == 0) dst[w] = m;
    }
}

// ---------------------------------------------------------------------------
// spmm: C[M, D] = sparse(S) @ W, bitwise-identical to sequential fp32 fma.
// CTA: 512 threads = 16 warps. Each warp: 8 rows x 128 cols (float4/lane).
// W slab: chunks of 128 p x 128 cols in smem, double-buffered cp.async.
// ---------------------------------------------------------------------------
#define WARPS      16
#define CTA_ROWS   128          // 16 warps * 8 rows
#define DTILE      128
#define PCHUNK     128
#define NCHUNK     (PP / PCHUNK)            // 8
#define SLAB_FLOATS (PCHUNK * DTILE)        // 16384 floats = 64 KB
#define SMEM_SPMM  (2 * SLAB_FLOATS * 4)    // 128 KB

__device__ __forceinline__ uint32_t smem_u32(const void* p) {
    uint32_t a;
    asm("{ .reg .u64 t; cvta.to.shared.u64 t, %1; cvt.u32.u64 %0, t; }" : "=r"(a) : "l"(p));
    return a;
}
__device__ __forceinline__ void cp16(uint32_t dst, const void* src) {
    asm volatile("cp.async.cg.shared.global [%0], [%1], 16;" :: "r"(dst), "l"(src));
}
#define CP_COMMIT() asm volatile("cp.async.commit_group;" ::: "memory")
#define CP_WAIT(n)  asm volatile("cp.async.wait_group %0;" :: "n"(n) : "memory")

__global__ __launch_bounds__(512, 1)
void spmm_kernel(const uint32_t* __restrict__ bits,   // [MM, 32]
                 const float* __restrict__ W,         // [PP, DD]
                 float* __restrict__ C)               // [MM, DD]
{
    extern __shared__ __align__(16) float slab[];     // [2][PCHUNK][DTILE]
    const int tid  = threadIdx.x;
    const int warp = tid >> 5;
    const int lane = tid & 31;
    const int bn = blockIdx.x * DTILE;
    const int bm = blockIdx.y * CTA_ROWS;
    const int row0 = bm + warp * 8;

    // Accumulators: 8 rows x 4 cols per lane. Start at +0.0 like reference.
    float4 acc[8];
    #pragma unroll
    for (int r = 0; r < 8; r++) acc[r] = make_float4(0.f, 0.f, 0.f, 0.f);

    // Async chunk loader: chunk c -> stage s. 512 threads x 8 float4 = 64 KB.
    auto load_chunk = [&](int c, int s) {
        const float* src = W + (size_t)(c * PCHUNK) * DD + bn;
        const uint32_t dst = smem_u32(slab) + s * (SLAB_FLOATS * 4);
        #pragma unroll
        for (int i = 0; i < 8; i++) {
            const int idx = tid + i * 512;            // 0..4095 float4s
            const int r = idx >> 5, c4 = idx & 31;
            cp16(dst + (r * DTILE + c4 * 4) * 4, src + (size_t)r * DD + c4 * 4);
        }
        CP_COMMIT();
    };

    load_chunk(0, 0);

    for (int c = 0; c < NCHUNK; c++) {
        CP_WAIT(0);          // chunk c resident
        __syncthreads();     // and all warps done with the other stage
        if (c + 1 < NCHUNK) load_chunk(c + 1, (c + 1) & 1);

        const float* sl = slab + (c & 1) * SLAB_FLOATS;

        #pragma unroll
        for (int r = 0; r < 8; r++) {
            // 4 bitmask words for this row's 128-p chunk (broadcast load).
            const uint4 wb = *(const uint4*)(bits + (size_t)(row0 + r) * (PP / 32) + c * 4);
            float4 a = acc[r];
            #pragma unroll
            for (int wd = 0; wd < 4; wd++) {
                uint32_t m = (wd == 0) ? wb.x : (wd == 1) ? wb.y : (wd == 2) ? wb.z : wb.w;
                const float* base = sl + (wd * 32) * DTILE + lane * 4;
                while (m) {                      // ascending p within word
                    const int b = __ffs(m) - 1;
                    m &= m - 1;
                    const float4 wv = *(const float4*)(base + b * DTILE);
                    a.x += wv.x; a.y += wv.y; a.z += wv.z; a.w += wv.w;
                }
            }
            acc[r] = a;
        }
        __syncthreads();     // done reading stage (c&1) before it is re-filled
    }

    // Epilogue: coalesced float4 stores.
    #pragma unroll
    for (int r = 0; r < 8; r++)
        *(float4*)&C[(size_t)(row0 + r) * DD + bn + lane * 4] = acc[r];
}

// ---------------------------------------------------------------------------
// LIF scan: unroll-by-8 with batched streaming loads for MLP.
// ---------------------------------------------------------------------------
__global__ __launch_bounds__(256)
void lif_scan_kernel(const float* __restrict__ cur,
                     float* __restrict__ vout,
                     float* __restrict__ sout)
{
    const int idx = blockIdx.x * blockDim.x + threadIdx.x;   // 0 .. B*D-1
    const int b = idx >> 10;
    const int d = idx & 1023;
    const size_t base = (size_t)b * TT * DD + d;

    float v = 0.0f;
    for (int t0 = 0; t0 < TT; t0 += 8) {
        float c[8];
        #pragma unroll
        for (int i = 0; i < 8; i++)
            c[i] = __ldcg(cur + base + (size_t)(t0 + i) * DD);
        #pragma unroll
        for (int i = 0; i < 8; i++) {
            const size_t off = base + (size_t)(t0 + i) * DD;
            const float v_new = fmaf(DECAY, v, c[i]);
            const bool sp = (v_new >= V_TH);
            __stcg(vout + off, v_new);
            __stcg(sout + off, sp ? 1.0f : 0.0f);
            v = sp ? 0.0f : v_new;               // v_new*(1-s) bitwise (v_new>0 when sp)
        }
    }
}

// ---------------------------------------------------------------------------
extern "C" void kernel_launch(void* const* d_in, const int* in_sizes, int n_in,
                              void* d_out, int out_size)
{
    const float* spikes  = (const float*)d_in[1];
    const float* weights = (const float*)d_in[2];
    float* out = (float*)d_out;

    float* currents;
    uint32_t* bits;
    cudaGetSymbolAddress((void**)&currents, g_currents);
    cudaGetSymbolAddress((void**)&bits, g_bits);

    // 1) spikes -> bitmask
    prep_bits<<<MM / 8, 256>>>(spikes, bits);

    // 2) exact sparse GEMM
    cudaFuncSetAttribute(spmm_kernel, cudaFuncAttributeMaxDynamicSharedMemorySize, SMEM_SPMM);
    dim3 grid(DD / DTILE, MM / CTA_ROWS);   // (8, 128)
    spmm_kernel<<<grid, 512, SMEM_SPMM>>>(bits, weights, currents);

    // 3) LIF scan
    const size_t n_elem = (size_t)BATCH * TT * DD;
    lif_scan_kernel<<<(BATCH * DD) / 256, 256>>>(currents, out, out + n_elem);
}